// round 16
// baseline (speedup 1.0000x reference)
#include <cuda_runtime.h>
#include <cuda_bf16.h>
#include <cstdint>

// ForceGrid R16: TMA-fed deposit. Particles stream into smem via
// cp.async.bulk (TMA engine, bypasses the L1tex LSU wavefront queue that the
// REDGs contend on); threads consume via conflict-free LDS and issue
// evict_last-pinned red.add. Index path replicates XLA bit-exactly:
// fi5 = RN(RN(RN(x+10) * 12.75f) + 0.5f), trunc, bounds-check.

#define GRID_N 256
#define CHUNK 2048                    // particles per stage
#define THREADS 256
#define PER_THREAD (CHUNK / THREADS)  // 8
#define POS_BYTES (CHUNK * 12)        // 24576
#define W_BYTES   (CHUNK * 4)         // 8192
#define STAGE_BYTES (POS_BYTES + W_BYTES)  // 32768
#define SMEM_MBAR (2 * STAGE_BYTES)   // 65536
#define SMEM_TOTAL (SMEM_MBAR + 64)

__device__ __forceinline__ uint64_t make_evict_last_policy() {
    uint64_t pol;
    asm volatile("createpolicy.fractional.L2::evict_last.b64 %0, 1.0;" : "=l"(pol));
    return pol;
}

__device__ __forceinline__ void deposit_one(float x, float y, float z, float w,
                                            float* __restrict__ grid,
                                            uint64_t pol) {
    const float R = 12.75f;  // RN(1 / RN(20/255)) == 12.75 exactly
    float fx = __fadd_rn(__fmul_rn(__fadd_rn(x, 10.0f), R), 0.5f);
    float fy = __fadd_rn(__fmul_rn(__fadd_rn(y, 10.0f), R), 0.5f);
    float fz = __fadd_rn(__fmul_rn(__fadd_rn(z, 10.0f), R), 0.5f);
    int ix = (int)fx;   // trunc toward zero == astype(int32)
    int iy = (int)fy;
    int iz = (int)fz;
    if (((unsigned)ix < GRID_N) & ((unsigned)iy < GRID_N) & ((unsigned)iz < GRID_N)) {
        int flat = (ix * GRID_N + iy) * GRID_N + iz;
        asm volatile("red.global.L2::cache_hint.add.f32 [%0], %1, %2;"
                     :: "l"(grid + flat), "f"(w), "l"(pol) : "memory");
    }
}

__device__ __forceinline__ uint32_t smem_u32(const void* p) {
    uint32_t a;
    asm("{ .reg .u64 t; cvta.to.shared.u64 t, %1; cvt.u32.u64 %0, t; }"
        : "=r"(a) : "l"(p));
    return a;
}

__device__ __forceinline__ void mbar_init(uint32_t mbar, uint32_t cnt) {
    asm volatile("mbarrier.init.shared.b64 [%0], %1;" :: "r"(mbar), "r"(cnt) : "memory");
}
__device__ __forceinline__ void mbar_expect_tx(uint32_t mbar, uint32_t bytes) {
    asm volatile("mbarrier.arrive.expect_tx.shared.b64 _, [%0], %1;"
                 :: "r"(mbar), "r"(bytes) : "memory");
}
__device__ __forceinline__ void mbar_wait(uint32_t mbar, uint32_t parity) {
    asm volatile("{\n\t.reg .pred P;\n"
                 "W%=:\n\t"
                 "mbarrier.try_wait.parity.acquire.cta.shared::cta.b64 P, [%0], %1;\n\t"
                 "@!P bra W%=;\n\t}"
                 :: "r"(mbar), "r"(parity) : "memory");
}
__device__ __forceinline__ void bulk_g2s(uint32_t dst, const void* src,
                                         uint32_t bytes, uint32_t mbar) {
    asm volatile("cp.async.bulk.shared::cta.global.mbarrier::complete_tx::bytes "
                 "[%0], [%1], %2, [%3];"
                 :: "r"(dst), "l"(src), "r"(bytes), "r"(mbar) : "memory");
}

// Zero the grid with 256-bit evict_last-policy stores (L2 pin, R6 win).
__global__ void __launch_bounds__(256)
forcegrid_zero_kernel(float* __restrict__ grid, int n8) {
    int i = blockIdx.x * blockDim.x + threadIdx.x;
    int stride = gridDim.x * blockDim.x;
    const float z = 0.0f;
    const uint64_t pol = make_evict_last_policy();
    for (; i < n8; i += stride) {
        asm volatile(
            "st.global.L2::cache_hint.v8.f32 [%0], {%1,%2,%3,%4,%5,%6,%7,%8}, %9;"
            :: "l"(grid + 8 * (size_t)i),
               "f"(z), "f"(z), "f"(z), "f"(z), "f"(z), "f"(z), "f"(z), "f"(z),
               "l"(pol)
            : "memory");
    }
}

__global__ void __launch_bounds__(THREADS)
forcegrid_deposit_kernel(const float* __restrict__ positions,
                         const float* __restrict__ weights,
                         float* __restrict__ grid,
                         int n_particles, int nchunks) {
    extern __shared__ char smem[];
    const uint32_t sbase = smem_u32(smem);
    const int tid = threadIdx.x;
    const uint64_t pol = make_evict_last_policy();

    if (tid == 0) {
        mbar_init(sbase + SMEM_MBAR + 0, 1);
        mbar_init(sbase + SMEM_MBAR + 8, 1);
    }
    __syncthreads();

    // Prologue: kick off loads for this CTA's first two chunks.
    if (tid == 0) {
        int c0 = blockIdx.x;
        int c1 = blockIdx.x + gridDim.x;
        if (c0 < nchunks) {
            uint32_t mb = sbase + SMEM_MBAR + 0;
            mbar_expect_tx(mb, STAGE_BYTES);
            bulk_g2s(sbase, positions + (size_t)c0 * CHUNK * 3, POS_BYTES, mb);
            bulk_g2s(sbase + POS_BYTES, weights + (size_t)c0 * CHUNK, W_BYTES, mb);
        }
        if (c1 < nchunks) {
            uint32_t mb = sbase + SMEM_MBAR + 8;
            mbar_expect_tx(mb, STAGE_BYTES);
            bulk_g2s(sbase + STAGE_BYTES, positions + (size_t)c1 * CHUNK * 3, POS_BYTES, mb);
            bulk_g2s(sbase + STAGE_BYTES + POS_BYTES, weights + (size_t)c1 * CHUNK, W_BYTES, mb);
        }
    }

    int i = 0;
    for (int c = blockIdx.x; c < nchunks; c += gridDim.x, i++) {
        const int s = i & 1;
        const int ph = (i >> 1) & 1;
        const uint32_t mb = sbase + SMEM_MBAR + 8 * s;
        mbar_wait(mb, ph);

        const float* spos = (const float*)(smem + s * STAGE_BYTES);
        const float* sw   = (const float*)(smem + s * STAGE_BYTES + POS_BYTES);

        #pragma unroll
        for (int k = 0; k < PER_THREAD; k++) {
            int j = tid + THREADS * k;        // conflict-free: bank (3*lane)%32
            float x = spos[3 * j + 0];
            float y = spos[3 * j + 1];
            float z = spos[3 * j + 2];
            float w = sw[j];
            deposit_one(x, y, z, w, grid, pol);
        }
        __syncthreads();                       // all lanes done with stage s

        if (tid == 0) {
            int c2 = c + 2 * gridDim.x;        // refill stage s for iter i+2
            if (c2 < nchunks) {
                mbar_expect_tx(mb, STAGE_BYTES);
                bulk_g2s(sbase + s * STAGE_BYTES,
                         positions + (size_t)c2 * CHUNK * 3, POS_BYTES, mb);
                bulk_g2s(sbase + s * STAGE_BYTES + POS_BYTES,
                         weights + (size_t)c2 * CHUNK, W_BYTES, mb);
            }
        }
    }

    // Tail (n % CHUNK): block 0, parallel across its threads, plain loads.
    if (blockIdx.x == 0) {
        for (int p = nchunks * CHUNK + tid; p < n_particles; p += THREADS) {
            deposit_one(__ldcs(&positions[3 * p + 0]), __ldcs(&positions[3 * p + 1]),
                        __ldcs(&positions[3 * p + 2]), __ldcs(&weights[p]), grid, pol);
        }
    }
}

extern "C" void kernel_launch(void* const* d_in, const int* in_sizes, int n_in,
                              void* d_out, int out_size) {
    const float* positions = (const float*)d_in[0];   // [N,3] f32
    const float* weights   = (const float*)d_in[1];   // [N]   f32
    float* grid = (float*)d_out;                      // 256^3 f32

    int n_particles = in_sizes[1];                    // N from weights
    int nchunks = n_particles / CHUNK;

    // Zero + L2-pin the grid (out_size = 256^3, divisible by 8).
    forcegrid_zero_kernel<<<148 * 4, 256, 0, 0>>>(grid, out_size / 8);

    static bool attr_set = false;
    if (!attr_set) {
        cudaFuncSetAttribute(forcegrid_deposit_kernel,
                             cudaFuncAttributeMaxDynamicSharedMemorySize, SMEM_TOTAL);
        attr_set = true;
    }

    // 3 CTAs/SM by smem (3 x ~64KB < 228KB); persistent grid-stride over chunks.
    int blocks = 148 * 3;
    if (blocks > nchunks && nchunks > 0) blocks = nchunks;
    if (nchunks == 0) blocks = 1;
    forcegrid_deposit_kernel<<<blocks, THREADS, SMEM_TOTAL, 0>>>(
        positions, weights, grid, n_particles, nchunks);
}

// round 17
// speedup vs baseline: 1.1908x; 1.1908x over previous
#include <cuda_runtime.h>
#include <cuda_bf16.h>
#include <cstdint>

// ForceGrid (final, converged): NGP deposit of 10M particles into a 256^3 grid.
// Index path replicates XLA bit-exactly: fi5 = RN(RN(RN(x+10) * 12.75f) + 0.5f)
// (reciprocal-mul, three separately-rounded ops), trunc, bounds-check, red.add.
// Perf: grid zeroed+pinned in L2 via evict_last policy stores; reductions carry
// the same evict_last cache hint -> zero random DRAM sector fetches (-12us).
// Deposit: persistent grid-stride, double-buffered LDG.128 quads.
// Floor: L1tex/LTS REDG wavefront serialization — proven insensitive to MLP,
// occupancy, pipelining, vector width, predication, and TMA feeding (R4-R16).

#define GRID_N 256

__device__ __forceinline__ uint64_t make_evict_last_policy() {
    uint64_t pol;
    asm volatile("createpolicy.fractional.L2::evict_last.b64 %0, 1.0;" : "=l"(pol));
    return pol;
}

__device__ __forceinline__ void deposit_one(float x, float y, float z, float w,
                                            float* __restrict__ grid,
                                            uint64_t pol) {
    const float R = 12.75f;  // RN(1 / RN(20/255)) == 12.75 exactly
    float fx = __fadd_rn(__fmul_rn(__fadd_rn(x, 10.0f), R), 0.5f);
    float fy = __fadd_rn(__fmul_rn(__fadd_rn(y, 10.0f), R), 0.5f);
    float fz = __fadd_rn(__fmul_rn(__fadd_rn(z, 10.0f), R), 0.5f);
    int ix = (int)fx;   // trunc toward zero == astype(int32)
    int iy = (int)fy;
    int iz = (int)fz;
    if (((unsigned)ix < GRID_N) & ((unsigned)iy < GRID_N) & ((unsigned)iz < GRID_N)) {
        int flat = (ix * GRID_N + iy) * GRID_N + iz;
        // Reduction with L2 evict_last cache hint: keeps grid lines resident.
        asm volatile("red.global.L2::cache_hint.add.f32 [%0], %1, %2;"
                     :: "l"(grid + flat), "f"(w), "l"(pol) : "memory");
    }
}

// Zero the grid with 256-bit evict_last-policy stores: lines enter L2
// dirty + pinned so deposit-phase atomics never fetch grid sectors from DRAM.
__global__ void __launch_bounds__(256)
forcegrid_zero_kernel(float* __restrict__ grid, int n8) {
    int i = blockIdx.x * blockDim.x + threadIdx.x;
    int stride = gridDim.x * blockDim.x;
    const float z = 0.0f;
    const uint64_t pol = make_evict_last_policy();
    for (; i < n8; i += stride) {
        asm volatile(
            "st.global.L2::cache_hint.v8.f32 [%0], {%1,%2,%3,%4,%5,%6,%7,%8}, %9;"
            :: "l"(grid + 8 * (size_t)i),
               "f"(z), "f"(z), "f"(z), "f"(z), "f"(z), "f"(z), "f"(z), "f"(z),
               "l"(pol)
            : "memory");
    }
}

__global__ void __launch_bounds__(256)
forcegrid_deposit_kernel(const float4* __restrict__ pos4,
                         const float4* __restrict__ w4,
                         const float*  __restrict__ pos_scalar,
                         const float*  __restrict__ w_scalar,
                         float* __restrict__ grid,
                         int n_particles) {
    const int nq = n_particles >> 2;                 // full quads
    const int stride = gridDim.x * blockDim.x;
    int q = blockIdx.x * blockDim.x + threadIdx.x;
    const uint64_t pol = make_evict_last_policy();

    // Software pipeline: cur regs hold quad q, next loads issue before deposits.
    float4 a, b, c, w;
    bool have = (q < nq);
    if (have) {
        a = __ldcs(&pos4[3 * q + 0]);
        b = __ldcs(&pos4[3 * q + 1]);
        c = __ldcs(&pos4[3 * q + 2]);
        w = __ldcs(&w4[q]);
    }
    while (have) {
        const int qn = q + stride;
        const bool haven = (qn < nq);
        float4 an, bn, cn, wn;
        if (haven) {                                  // prefetch next quad
            an = __ldcs(&pos4[3 * qn + 0]);
            bn = __ldcs(&pos4[3 * qn + 1]);
            cn = __ldcs(&pos4[3 * qn + 2]);
            wn = __ldcs(&w4[qn]);
        }
        deposit_one(a.x, a.y, a.z, w.x, grid, pol);
        deposit_one(a.w, b.x, b.y, w.y, grid, pol);
        deposit_one(b.z, b.w, c.x, w.z, grid, pol);
        deposit_one(c.y, c.z, c.w, w.w, grid, pol);
        a = an; b = bn; c = cn; w = wn;               // rotate buffers
        q = qn; have = haven;
    }

    // tail (n_particles % 4 != 0) — single thread, scalar path
    if (blockIdx.x == 0 && threadIdx.x == 0) {
        for (int p = nq * 4; p < n_particles; p++) {
            deposit_one(pos_scalar[3 * p + 0], pos_scalar[3 * p + 1],
                        pos_scalar[3 * p + 2], w_scalar[p], grid, pol);
        }
    }
}

extern "C" void kernel_launch(void* const* d_in, const int* in_sizes, int n_in,
                              void* d_out, int out_size) {
    const float* positions = (const float*)d_in[0];   // [N,3] f32
    const float* weights   = (const float*)d_in[1];   // [N]   f32
    float* grid = (float*)d_out;                      // 256^3 f32

    int n_particles = in_sizes[1];                    // N from weights

    int threads = 256;

    // Zero + L2-pin the grid (out_size = 256^3, divisible by 8).
    int n8 = out_size / 8;
    int zblocks = 148 * 4;
    forcegrid_zero_kernel<<<zblocks, threads, 0, 0>>>(grid, n8);

    // Persistent deposit with grid-stride double-buffer (best measured config).
    int blocks = 148 * 8;
    forcegrid_deposit_kernel<<<blocks, threads, 0, 0>>>(
        (const float4*)positions, (const float4*)weights,
        positions, weights, grid, n_particles);
}